// round 2
// baseline (speedup 1.0000x reference)
#include <cuda_runtime.h>

#define BB 256
#define DD 1024
#define LOG2E 1.4426950408889634f

// scratch for Q, K, V (3 MB) — __device__ global per allocation rules
__device__ float g_QKV[3 * BB * DD];

__device__ __forceinline__ float ex2f(float x) {
    float y; asm("ex2.approx.ftz.f32 %0, %1;" : "=f"(y) : "f"(x)); return y;
}
__device__ __forceinline__ unsigned long long pk2(float lo, float hi) {
    unsigned long long r; asm("mov.b64 %0, {%1,%2};" : "=l"(r) : "f"(lo), "f"(hi)); return r;
}
__device__ __forceinline__ void upk2(unsigned long long v, float &lo, float &hi) {
    asm("mov.b64 {%0,%1}, %2;" : "=f"(lo), "=f"(hi) : "l"(v));
}
__device__ __forceinline__ unsigned long long ffma2(unsigned long long a, unsigned long long b, unsigned long long c) {
    unsigned long long d;
    asm("fma.rn.f32x2 %0, %1, %2, %3;" : "=l"(d) : "l"(a), "l"(b), "l"(c));
    return d;
}

// ---------------------------------------------------------------------------
// Kernel 1: QKV projection GEMMs.  out[b,n] = sum_k x[b,k]*W[n,k] + bias[n]
// Tile 64(m) x 64(n), K-step 32, 256 threads, 4x4 outputs/thread via f32x2,
// double-buffered shared memory.
// grid = (B/64=4, D/64=16, 3)   z selects (Wq,bq)->Q, (Wk,bk)->K, (Wv,bv)->V
// ---------------------------------------------------------------------------
#define TM 64
#define TN 64
#define TK 32
#define TPAD 4

__global__ __launch_bounds__(256) void gemm_qkv_kernel(
    const float* __restrict__ x,
    const float* __restrict__ Wq, const float* __restrict__ bq,
    const float* __restrict__ Wk, const float* __restrict__ bk,
    const float* __restrict__ Wv, const float* __restrict__ bv)
{
    const int z = blockIdx.z;
    const float* W    = (z == 0) ? Wq : (z == 1) ? Wk : Wv;
    const float* bias = (z == 0) ? bq : (z == 1) ? bk : bv;
    float* out = g_QKV + z * (BB * DD);

    __shared__ float xs[2][TK][TM + TPAD];   // [k][m]
    __shared__ float ws[2][TK][TN + TPAD];   // [k][n]

    const int t  = threadIdx.x;
    const int m0 = blockIdx.x * TM;
    const int n0 = blockIdx.y * TN;

    // loader mapping: each thread fetches 8 consecutive k's for one row
    const int ml = t >> 2;          // 0..63 (row within tile, for x: m, for W: n)
    const int kl = (t & 3) * 8;     // 0,8,16,24

    // compute mapping: 16x16 thread grid, 4m x 4n per thread
    const int tx = t & 15;
    const int ty = t >> 4;

    unsigned long long acc[4][2];
#pragma unroll
    for (int i = 0; i < 4; i++) { acc[i][0] = pk2(0.f, 0.f); acc[i][1] = pk2(0.f, 0.f); }

    float4 ax0, ax1, aw0, aw1;
    {
        const float* px = &x[(m0 + ml) * DD + kl];
        const float* pw = &W[(n0 + ml) * DD + kl];
        ax0 = *(const float4*)px;       ax1 = *(const float4*)(px + 4);
        aw0 = *(const float4*)pw;       aw1 = *(const float4*)(pw + 4);
    }
    int buf = 0;
#pragma unroll
    for (int j = 0; j < 4; j++) {
        xs[0][kl + j][ml]     = ((const float*)&ax0)[j];
        xs[0][kl + 4 + j][ml] = ((const float*)&ax1)[j];
        ws[0][kl + j][ml]     = ((const float*)&aw0)[j];
        ws[0][kl + 4 + j][ml] = ((const float*)&aw1)[j];
    }
    __syncthreads();

    const int NT = DD / TK;  // 32
    for (int kt = 0; kt < NT; kt++) {
        if (kt + 1 < NT) {
            const float* px = &x[(m0 + ml) * DD + (kt + 1) * TK + kl];
            const float* pw = &W[(n0 + ml) * DD + (kt + 1) * TK + kl];
            ax0 = *(const float4*)px;   ax1 = *(const float4*)(px + 4);
            aw0 = *(const float4*)pw;   aw1 = *(const float4*)(pw + 4);
        }
#pragma unroll
        for (int kk = 0; kk < TK; kk++) {
            float4 a = *(const float4*)&xs[buf][kk][ty * 4];
            ulonglong2 bp = *(const ulonglong2*)&ws[buf][kk][tx * 4];
            unsigned long long a0 = pk2(a.x, a.x);
            unsigned long long a1 = pk2(a.y, a.y);
            unsigned long long a2 = pk2(a.z, a.z);
            unsigned long long a3 = pk2(a.w, a.w);
            acc[0][0] = ffma2(a0, bp.x, acc[0][0]);  acc[0][1] = ffma2(a0, bp.y, acc[0][1]);
            acc[1][0] = ffma2(a1, bp.x, acc[1][0]);  acc[1][1] = ffma2(a1, bp.y, acc[1][1]);
            acc[2][0] = ffma2(a2, bp.x, acc[2][0]);  acc[2][1] = ffma2(a2, bp.y, acc[2][1]);
            acc[3][0] = ffma2(a3, bp.x, acc[3][0]);  acc[3][1] = ffma2(a3, bp.y, acc[3][1]);
        }
        if (kt + 1 < NT) {
            __syncthreads();
            buf ^= 1;
#pragma unroll
            for (int j = 0; j < 4; j++) {
                xs[buf][kl + j][ml]     = ((const float*)&ax0)[j];
                xs[buf][kl + 4 + j][ml] = ((const float*)&ax1)[j];
                ws[buf][kl + j][ml]     = ((const float*)&aw0)[j];
                ws[buf][kl + 4 + j][ml] = ((const float*)&aw1)[j];
            }
            __syncthreads();
        }
    }

    float4 bb = *(const float4*)&bias[n0 + tx * 4];
#pragma unroll
    for (int i = 0; i < 4; i++) {
        float r0, r1, r2, r3;
        upk2(acc[i][0], r0, r1);
        upk2(acc[i][1], r2, r3);
        float4 o;
        o.x = r0 + bb.x; o.y = r1 + bb.y; o.z = r2 + bb.z; o.w = r3 + bb.w;
        *(float4*)&out[(m0 + ty * 4 + i) * DD + n0 + tx * 4] = o;
    }
}

// ---------------------------------------------------------------------------
// Kernel 2: per-(b,i) scalar-softmax attention + residual.
//   logits_j = (Q[b,i]/scale) * K[b,j];  attn = softmax_j;  att = attn . V[b,:]
//   out[b,i] = att + x[b,i]     (RMSNorm applied by kernel 3, in-place)
// grid = 1024 blocks (b x i-quarter), 256 threads, one i per thread.
// K,V staged in shared as float2; inner loop is MUFU(EX2)-bound.
// ---------------------------------------------------------------------------
__global__ __launch_bounds__(256) void attn_kernel(
    const float* __restrict__ x,
    const float* __restrict__ scale_p,
    float* __restrict__ out)
{
    const int b     = blockIdx.x >> 2;
    const int ibase = (blockIdx.x & 3) << 8;
    const int t     = threadIdx.x;

    __shared__ float2 kv[DD];
    __shared__ float redmx[8], redmn[8];

    const float* Kp = g_QKV + BB * DD + b * DD;
    const float* Vp = g_QKV + 2 * BB * DD + b * DD;

    float mx = -1e30f, mn = 1e30f;
#pragma unroll
    for (int j = t; j < DD; j += 256) {
        float kx = Kp[j];
        float vy = Vp[j];
        kv[j] = make_float2(kx, vy);
        mx = fmaxf(mx, kx);
        mn = fminf(mn, kx);
    }
#pragma unroll
    for (int o = 16; o > 0; o >>= 1) {
        mx = fmaxf(mx, __shfl_xor_sync(0xFFFFFFFFu, mx, o));
        mn = fminf(mn, __shfl_xor_sync(0xFFFFFFFFu, mn, o));
    }
    if ((t & 31) == 0) { redmx[t >> 5] = mx; redmn[t >> 5] = mn; }
    __syncthreads();
    mx = redmx[0]; mn = redmn[0];
#pragma unroll
    for (int w = 1; w < 8; w++) { mx = fmaxf(mx, redmx[w]); mn = fminf(mn, redmn[w]); }

    const int   i   = ibase + t;
    const float cs  = LOG2E / scale_p[0];
    const float c2  = g_QKV[b * DD + i] * cs;     // Q scaled into log2 domain
    const float m2  = (c2 >= 0.f) ? c2 * mx : c2 * mn;   // row max in log2 domain
    const float nm2 = -m2;

    float s  = 0.f;
    float dn = 0.f;
#pragma unroll 8
    for (int j = 0; j < DD; j++) {
        float2 kvj = kv[j];                        // broadcast LDS.64
        float  e   = ex2f(__fmaf_rn(c2, kvj.x, nm2));
        s  += e;
        dn  = __fmaf_rn(e, kvj.y, dn);
    }

    out[b * DD + i] = dn / s + x[b * DD + i];
}

// ---------------------------------------------------------------------------
// Kernel 3: in-place RMSNorm over each row of out. grid = 256, 256 threads.
// ---------------------------------------------------------------------------
__global__ __launch_bounds__(256) void rmsnorm_kernel(
    float* __restrict__ out, const float* __restrict__ nw)
{
    const int b = blockIdx.x;
    const int t = threadIdx.x;
    __shared__ float red[8];

    float4 h = *(const float4*)&out[b * DD + t * 4];
    float local = h.x * h.x + h.y * h.y + h.z * h.z + h.w * h.w;
#pragma unroll
    for (int o = 16; o > 0; o >>= 1) local += __shfl_xor_sync(0xFFFFFFFFu, local, o);
    if ((t & 31) == 0) red[t >> 5] = local;
    __syncthreads();
    float tot = 0.f;
#pragma unroll
    for (int w = 0; w < 8; w++) tot += red[w];

    float r = rsqrtf(tot * (1.0f / DD) + 1e-6f);
    float4 w4 = *(const float4*)&nw[t * 4];
    float4 o;
    o.x = h.x * r * w4.x;
    o.y = h.y * r * w4.y;
    o.z = h.z * r * w4.z;
    o.w = h.w * r * w4.w;
    *(float4*)&out[b * DD + t * 4] = o;
}

extern "C" void kernel_launch(void* const* d_in, const int* in_sizes, int n_in,
                              void* d_out, int out_size)
{
    const float* x     = (const float*)d_in[0];
    const float* Wq    = (const float*)d_in[1];
    const float* bq    = (const float*)d_in[2];
    const float* Wk    = (const float*)d_in[3];
    const float* bk    = (const float*)d_in[4];
    const float* Wv    = (const float*)d_in[5];
    const float* bv    = (const float*)d_in[6];
    const float* scale = (const float*)d_in[7];
    const float* nw    = (const float*)d_in[8];
    float* out = (float*)d_out;

    dim3 ggrid(BB / TM, DD / TN, 3);
    gemm_qkv_kernel<<<ggrid, 256>>>(x, Wq, bq, Wk, bk, Wv, bv);
    attn_kernel<<<BB * 4, 256>>>(x, scale, out);
    rmsnorm_kernel<<<BB, 256>>>(out, nw);
}